// round 1
// baseline (speedup 1.0000x reference)
#include <cuda_runtime.h>
#include <cuda_bf16.h>
#include <cstdint>

// Problem dims (fixed by the reference)
#define BB   32      // batch
#define NN   4096    // nodes
#define CIN  128
#define COUT 128
#define MM   256     // spectral modes

// Scratch (device globals: allocation-guard safe)
__device__ float g_xspec[BB * MM * CIN];     // [b][m][c]   4 MB
__device__ float g_ospec[BB * MM * COUT];    // [b][m][o]   4 MB
__device__ float g_wt[MM * CIN * COUT];      // [m][c][o]  16.8 MB

// ---------------------------------------------------------------------------
// Stage A: x_spec[b][m][c] = sum_n U[n][m] * x[b][n][c]
// Per-batch GEMM: [M x N] (=U^T) @ [N x C]. K = 4096.
// Tiles: 64(m) x 64(c), BK=16. 256 threads, 4x4 micro-tile.
// Both operands are k-row-major in memory -> no transpose needed on load.
// ---------------------------------------------------------------------------
__global__ __launch_bounds__(256)
void kA(const float* __restrict__ U, const float* __restrict__ x) {
    __shared__ float As[16][64];   // [k][m]
    __shared__ float Bs[16][64];   // [k][c]

    const int m0 = blockIdx.x * 64;
    const int c0 = blockIdx.y * 64;
    const int b  = blockIdx.z;

    const int t  = threadIdx.x;
    const int tx = t & 15;         // c-quad
    const int ty = t >> 4;         // m-quad
    const int lr  = t >> 4;        // load row (k within tile), 0..15
    const int lc4 = t & 15;        // load col quad, 0..15

    const float* xb = x + (size_t)b * NN * CIN;

    float acc[4][4];
#pragma unroll
    for (int i = 0; i < 4; i++)
#pragma unroll
        for (int j = 0; j < 4; j++) acc[i][j] = 0.f;

    for (int k0 = 0; k0 < NN; k0 += 16) {
        float4 a4 = *(const float4*)(U  + (size_t)(k0 + lr) * MM  + m0 + lc4 * 4);
        float4 b4 = *(const float4*)(xb + (size_t)(k0 + lr) * CIN + c0 + lc4 * 4);
        *(float4*)&As[lr][lc4 * 4] = a4;
        *(float4*)&Bs[lr][lc4 * 4] = b4;
        __syncthreads();

#pragma unroll
        for (int kk = 0; kk < 16; kk++) {
            float4 av = *(const float4*)&As[kk][ty * 4];
            float4 bv = *(const float4*)&Bs[kk][tx * 4];
            float a[4] = {av.x, av.y, av.z, av.w};
            float bb[4] = {bv.x, bv.y, bv.z, bv.w};
#pragma unroll
            for (int i = 0; i < 4; i++)
#pragma unroll
                for (int j = 0; j < 4; j++) acc[i][j] += a[i] * bb[j];
        }
        __syncthreads();
    }

    float* outp = g_xspec + ((size_t)b * MM) * CIN;
#pragma unroll
    for (int i = 0; i < 4; i++)
#pragma unroll
        for (int j = 0; j < 4; j++)
            outp[(size_t)(m0 + ty * 4 + i) * CIN + c0 + tx * 4 + j] = acc[i][j];
}

// ---------------------------------------------------------------------------
// Stage T: transpose W_real[c][o][m] (m-contiguous) -> g_wt[m][c][o] (o-contig)
// Classic 32x32 smem transpose over the (o, m) plane per fixed c.
// ---------------------------------------------------------------------------
__global__ __launch_bounds__(256)
void kT(const float* __restrict__ W) {
    __shared__ float tile[32][33];
    const int c  = blockIdx.x;           // 0..127
    const int o0 = blockIdx.y * 32;      // 0..96
    const int m0 = blockIdx.z * 32;      // 0..224
    const int tx = threadIdx.x;          // 0..31
    const int ty = threadIdx.y;          // 0..7

#pragma unroll
    for (int j = 0; j < 32; j += 8) {
        // read coalesced in m
        tile[ty + j][tx] = W[((size_t)c * COUT + (o0 + ty + j)) * MM + m0 + tx];
    }
    __syncthreads();
#pragma unroll
    for (int j = 0; j < 32; j += 8) {
        // write coalesced in o
        g_wt[((size_t)(m0 + ty + j) * CIN + c) * COUT + o0 + tx] = tile[tx][ty + j];
    }
}

// ---------------------------------------------------------------------------
// Stage B: ospec[b][m][o] = sum_c xspec[b][m][c] * Wt[m][c][o]
// One block per mode m. Output [32 b x 128 o], K = 128 (chunked by 32).
// 256 threads: thread -> (b-quad = (t>>5)*4, o-quad = (t&31)*4), 4x4 micro.
// ---------------------------------------------------------------------------
__global__ __launch_bounds__(256)
void kB() {
    __shared__ float xsT[CIN][33];     // [c][b], pad for conflict-free fill
    __shared__ float Ws[32][COUT];     // chunk of Wt[m]: [c'][o]

    const int m = blockIdx.x;
    const int t = threadIdx.x;
    const int o4 = (t & 31) * 4;       // 0..124
    const int b0 = (t >> 5) * 4;       // 0..28

    // stage xspec[b][m][:] transposed into xsT[c][b]
    for (int idx = t; idx < BB * CIN; idx += 256) {
        int b = idx / CIN, c = idx % CIN;
        xsT[c][b] = g_xspec[((size_t)b * MM + m) * CIN + c];
    }

    float acc[4][4];
#pragma unroll
    for (int i = 0; i < 4; i++)
#pragma unroll
        for (int j = 0; j < 4; j++) acc[i][j] = 0.f;

    const float* wtm = g_wt + (size_t)m * CIN * COUT;

    for (int cc = 0; cc < CIN; cc += 32) {
        __syncthreads();   // guard prev Ws reads (and xsT fill on iter 0)
        for (int idx = t; idx < 32 * COUT; idx += 256) {
            int cr = idx >> 7, o = idx & 127;
            Ws[cr][o] = wtm[(size_t)(cc + cr) * COUT + o];
        }
        __syncthreads();

#pragma unroll
        for (int c = 0; c < 32; c++) {
            float xv[4];
#pragma unroll
            for (int i = 0; i < 4; i++) xv[i] = xsT[cc + c][b0 + i]; // broadcast
            float4 wv = *(const float4*)&Ws[c][o4];
            float w[4] = {wv.x, wv.y, wv.z, wv.w};
#pragma unroll
            for (int i = 0; i < 4; i++)
#pragma unroll
                for (int j = 0; j < 4; j++) acc[i][j] += xv[i] * w[j];
        }
    }

#pragma unroll
    for (int i = 0; i < 4; i++)
#pragma unroll
        for (int j = 0; j < 4; j++)
            g_ospec[((size_t)(b0 + i) * MM + m) * COUT + o4 + j] = acc[i][j];
}

// ---------------------------------------------------------------------------
// Stage C: out[b][n][o] = sum_m U[n][m] * ospec[b][m][o]
// Per-batch GEMM: [N x M] @ [M x O]. K = 256.
// Tiles: 64(n) x 64(o), BK=16. U tile stored transposed (As[k][n], pad 68).
// ---------------------------------------------------------------------------
__global__ __launch_bounds__(256)
void kC(const float* __restrict__ U, float* __restrict__ out) {
    __shared__ float As[16][68];   // [k=m][n], row stride 68 keeps 16B align
    __shared__ float Bs[16][64];   // [k=m][o]

    const int n0 = blockIdx.x * 64;
    const int o0 = blockIdx.y * 64;
    const int b  = blockIdx.z;

    const int t  = threadIdx.x;
    const int tx = t & 15;
    const int ty = t >> 4;

    const int an = t >> 2;         // 0..63  (n row for A load)
    const int ak = t & 3;          // 0..3   (k quad for A load)
    const int br  = t >> 4;        // 0..15  (k row for B load)
    const int bc4 = t & 15;        // 0..15  (o quad for B load)

    const float* osb = g_ospec + (size_t)b * MM * COUT;

    float acc[4][4];
#pragma unroll
    for (int i = 0; i < 4; i++)
#pragma unroll
        for (int j = 0; j < 4; j++) acc[i][j] = 0.f;

    for (int k0 = 0; k0 < MM; k0 += 16) {
        float4 u4 = *(const float4*)(U + (size_t)(n0 + an) * MM + k0 + ak * 4);
        // transpose into As[k][n]
        As[ak * 4 + 0][an] = u4.x;
        As[ak * 4 + 1][an] = u4.y;
        As[ak * 4 + 2][an] = u4.z;
        As[ak * 4 + 3][an] = u4.w;
        float4 b4 = *(const float4*)(osb + (size_t)(k0 + br) * COUT + o0 + bc4 * 4);
        *(float4*)&Bs[br][bc4 * 4] = b4;
        __syncthreads();

#pragma unroll
        for (int kk = 0; kk < 16; kk++) {
            float4 av = *(const float4*)&As[kk][ty * 4];
            float4 bv = *(const float4*)&Bs[kk][tx * 4];
            float a[4] = {av.x, av.y, av.z, av.w};
            float bb[4] = {bv.x, bv.y, bv.z, bv.w};
#pragma unroll
            for (int i = 0; i < 4; i++)
#pragma unroll
                for (int j = 0; j < 4; j++) acc[i][j] += a[i] * bb[j];
        }
        __syncthreads();
    }

    float* ob = out + (size_t)b * NN * COUT;
#pragma unroll
    for (int i = 0; i < 4; i++)
#pragma unroll
        for (int j = 0; j < 4; j++)
            ob[(size_t)(n0 + ty * 4 + i) * COUT + o0 + tx * 4 + j] = acc[i][j];
}

// ---------------------------------------------------------------------------
// Launch: A and T are independent; B needs both; C needs B.
// Sequential launches on the capture stream give the needed ordering.
// ---------------------------------------------------------------------------
extern "C" void kernel_launch(void* const* d_in, const int* in_sizes, int n_in,
                              void* d_out, int out_size) {
    const float* x = (const float*)d_in[0];       // [32,4096,128]
    const float* U = (const float*)d_in[1];       // [4096,256]
    const float* W = (const float*)d_in[2];       // [128,128,256]
    // d_in[3] = W_imag: mathematically dead (Re(real * complex) uses only W_real)
    float* out = (float*)d_out;                   // [32,4096,128]

    kA<<<dim3(MM / 64, CIN / 64, BB), 256>>>(U, x);
    kT<<<dim3(CIN, COUT / 32, MM / 32), dim3(32, 8)>>>(W);
    kB<<<MM, 256>>>();
    kC<<<dim3(NN / 64, COUT / 64, BB), 256>>>(U, out);
}

// round 5
// speedup vs baseline: 1.8646x; 1.8646x over previous
#include <cuda_runtime.h>
#include <cstdint>

#define BB   32
#define NN   4096
#define CIN  128
#define COUT 128
#define MM   256

__device__ __forceinline__ uint32_t smem_to_u32(const void* p) {
    uint32_t a;
    asm("{ .reg .u64 t; cvta.to.shared.u64 t, %1; cvt.u32.u64 %0, t; }" : "=r"(a) : "l"(p));
    return a;
}
__device__ __forceinline__ float tf32r(float f) {
    uint32_t u;
    asm("cvt.rna.tf32.f32 %0, %1;" : "=r"(u) : "f"(f));
    return __uint_as_float(u);
}

// ===========================================================================
// Scratch (device globals — allocation-guard safe)
// ===========================================================================
__device__ __align__(16) float g_Ur[NN * MM];                  // tf32-rounded U  [n][m]
__device__ __align__(16) float g_xr[(size_t)BB * NN * CIN];    // tf32-rounded x  [b][n][c]
__device__ __align__(16) float g_xspec[BB * MM * CIN];         // [b][m][c] fp32
__device__ __align__(16) float g_wt[MM * CIN * COUT];          // [m][c][o] fp32
__device__ __align__(16) float g_ospec[BB * MM * COUT];        // [b][m][o] tf32-rounded

// ===========================================================================
// kRound: dst = round_to_nearest_tf32(src), vectorized
// ===========================================================================
__global__ __launch_bounds__(256) void kRound(const float* __restrict__ src,
                                              float* __restrict__ dst, int n4) {
    for (int i = blockIdx.x * blockDim.x + threadIdx.x; i < n4; i += gridDim.x * blockDim.x) {
        float4 v = ((const float4*)src)[i];
        v.x = tf32r(v.x); v.y = tf32r(v.y); v.z = tf32r(v.z); v.w = tf32r(v.w);
        ((float4*)dst)[i] = v;
    }
}

// ===========================================================================
// kT: W_real[c][o][m] -> g_wt[m][c][o]  (fp32; stage B is fp32 math)
// ===========================================================================
__global__ __launch_bounds__(256) void kT(const float* __restrict__ W) {
    __shared__ float tile[32][33];
    const int c = blockIdx.x, o0 = blockIdx.y * 32, m0 = blockIdx.z * 32;
    const int tx = threadIdx.x, ty = threadIdx.y;
#pragma unroll
    for (int j = 0; j < 32; j += 8)
        tile[ty + j][tx] = W[((size_t)c * COUT + (o0 + ty + j)) * MM + m0 + tx];
    __syncthreads();
#pragma unroll
    for (int j = 0; j < 32; j += 8)
        g_wt[((size_t)(m0 + ty + j) * CIN + c) * COUT + o0 + tx] = tile[tx][ty + j];
}

// ===========================================================================
// Unified tf32 tensor-core GEMM:  C[i][j] = sum_k A(i,k) * B[bz][k][j]
//   ATRANS=true : gA layout [K][lda]   (A(i,k) = gA[k*lda + i])   -- stage A (A=U)
//   ATRANS=false: gA layout [M][lda]   (A(i,k) = gA[i*lda + k])   -- stage C (A=U)
//   gB layout [bz][K][ldb] (row k contiguous in j)
// CTA tile 128(i) x 64(j), BK=32, 8 warps of 32x32, double-buffered cp.async.
// ===========================================================================
template <bool ATRANS, int KTOT>
__global__ __launch_bounds__(256) void kGemm(
    const float* __restrict__ gA, const float* __restrict__ gB, float* __restrict__ gC,
    int lda, int ldb, int ldc, size_t strideB, size_t strideC)
{
    constexpr int ASZ = ATRANS ? 32 * 136 : 128 * 36;   // padded floats
    constexpr int BSZ = 32 * 68;
    constexpr int BUFST = ASZ + BSZ;
    extern __shared__ float sm[];
    const uint32_t smU = smem_to_u32(sm);

    const int tid = threadIdx.x;
    const int i0 = blockIdx.x * 128, j0 = blockIdx.y * 64, bz = blockIdx.z;
    const float* gBb = gB + (size_t)bz * strideB;

    const int w = tid >> 5, lane = tid & 31;
    const int i_w = (w & 3) * 32, j_w = (w >> 2) * 32;
    const int r4 = lane >> 2, c4 = lane & 3;

    float acc[2][4][4];
#pragma unroll
    for (int mt = 0; mt < 2; mt++)
#pragma unroll
        for (int nt = 0; nt < 4; nt++)
#pragma unroll
            for (int q = 0; q < 4; q++) acc[mt][nt][q] = 0.f;

    // -------- async tile loader --------
    auto load = [&](int k0, int buf) {
        uint32_t aU = smU + (uint32_t)(buf * BUFST) * 4u;
        uint32_t bU = aU + (uint32_t)ASZ * 4u;
#pragma unroll
        for (int it = 0; it < 4; it++) {        // A: 4096 floats = 1024 x 16B
            int t4 = tid + it * 256;
            const float* src; uint32_t so;
            if (ATRANS) {
                int kr = t4 >> 5, cc = (t4 & 31) * 4;
                src = gA + (size_t)(k0 + kr) * lda + i0 + cc;
                so = (uint32_t)(kr * 136 + cc);
            } else {
                int rr = t4 >> 3, cc = (t4 & 7) * 4;
                src = gA + (size_t)(i0 + rr) * lda + k0 + cc;
                so = (uint32_t)(rr * 36 + cc);
            }
            asm volatile("cp.async.cg.shared.global [%0], [%1], 16;" :: "r"(aU + so * 4u), "l"(src));
        }
#pragma unroll
        for (int it = 0; it < 2; it++) {        // B: 2048 floats = 512 x 16B
            int t4 = tid + it * 256;
            int kr = t4 >> 4, cc = (t4 & 15) * 4;
            const float* src = gBb + (size_t)(k0 + kr) * ldb + j0 + cc;
            asm volatile("cp.async.cg.shared.global [%0], [%1], 16;"
                         :: "r"(bU + (uint32_t)(kr * 68 + cc) * 4u), "l"(src));
        }
        asm volatile("cp.async.commit_group;");
    };

    load(0, 0);
    constexpr int NCH = KTOT / 32;
    for (int ch = 0; ch < NCH; ch++) {
        const int buf = ch & 1;
        if (ch + 1 < NCH) {
            load((ch + 1) * 32, buf ^ 1);
            asm volatile("cp.async.wait_group 1;");
        } else {
            asm volatile("cp.async.wait_group 0;");
        }
        __syncthreads();

        const float* as = sm + buf * BUFST;
        const float* bs = as + ASZ;
#pragma unroll
        for (int kk = 0; kk < 32; kk += 8) {
            uint32_t a[2][4], bf[4][2];
#pragma unroll
            for (int mt = 0; mt < 2; mt++) {
                const int ib = i_w + mt * 16 + r4;
                if (ATRANS) {
                    const float* p0 = as + (kk + c4) * 136 + ib;       // A[m][k] from [k][m]
                    const float* p1 = p0 + 4 * 136;
                    a[mt][0] = __float_as_uint(p0[0]);   // (m,   k)
                    a[mt][1] = __float_as_uint(p0[8]);   // (m+8, k)
                    a[mt][2] = __float_as_uint(p1[0]);   // (m,   k+4)
                    a[mt][3] = __float_as_uint(p1[8]);   // (m+8, k+4)
                } else {
                    const float* p0 = as + ib * 36 + kk + c4;          // A[m][k] direct
                    const float* p1 = p0 + 8 * 36;
                    a[mt][0] = __float_as_uint(p0[0]);
                    a[mt][1] = __float_as_uint(p1[0]);
                    a[mt][2] = __float_as_uint(p0[4]);
                    a[mt][3] = __float_as_uint(p1[4]);
                }
            }
#pragma unroll
            for (int nt = 0; nt < 4; nt++) {
                const float* pb = bs + (kk + c4) * 68 + j_w + nt * 8 + r4;  // B col-major from [k][j]
                bf[nt][0] = __float_as_uint(pb[0]);
                bf[nt][1] = __float_as_uint(pb[4 * 68]);
            }
#pragma unroll
            for (int mt = 0; mt < 2; mt++)
#pragma unroll
                for (int nt = 0; nt < 4; nt++)
                    asm volatile(
                        "mma.sync.aligned.m16n8k8.row.col.f32.tf32.tf32.f32 "
                        "{%0,%1,%2,%3}, {%4,%5,%6,%7}, {%8,%9}, {%0,%1,%2,%3};"
                        : "+f"(acc[mt][nt][0]), "+f"(acc[mt][nt][1]),
                          "+f"(acc[mt][nt][2]), "+f"(acc[mt][nt][3])
                        : "r"(a[mt][0]), "r"(a[mt][1]), "r"(a[mt][2]), "r"(a[mt][3]),
                          "r"(bf[nt][0]), "r"(bf[nt][1]));
        }
        __syncthreads();
    }

    float* cb = gC + (size_t)bz * strideC;
#pragma unroll
    for (int mt = 0; mt < 2; mt++)
#pragma unroll
        for (int nt = 0; nt < 4; nt++) {
            const int r = i0 + i_w + mt * 16 + r4;
            const int c = j0 + j_w + nt * 8 + c4 * 2;
            float2 v0 = { acc[mt][nt][0], acc[mt][nt][1] };
            float2 v1 = { acc[mt][nt][2], acc[mt][nt][3] };
            *(float2*)&cb[(size_t)r * ldc + c] = v0;
            *(float2*)&cb[(size_t)(r + 8) * ldc + c] = v1;
        }
}

// ===========================================================================
// Stage B (fp32): ospec[b][m][o] = sum_c xspec[b][m][c] * wt[m][c][o]
// Stores tf32-rounded so stage C needs no in-loop cvt.
// ===========================================================================
__global__ __launch_bounds__(256) void kB() {
    __shared__ float xsT[CIN][33];
    __shared__ float Ws[32][COUT];

    const int m = blockIdx.x;
    const int t = threadIdx.x;
    const int o4 = (t & 31) * 4;
    const int b0 = (t >> 5) * 4;

    for (int idx = t; idx < BB * CIN; idx += 256) {
        int b = idx / CIN, c = idx % CIN;
        xsT[c][b] = g_xspec[((size_t)b * MM + m) * CIN + c];
    }

    float acc[4][4];
#pragma unroll
    for (int i = 0; i < 4; i++)
#pragma unroll
        for (int j = 0; j < 4; j++) acc[i][j] = 0.f;

    const float* wtm = g_wt + (size_t)m * CIN * COUT;
    for (int cc = 0; cc < CIN; cc += 32) {
        __syncthreads();
        for (int idx = t; idx < 32 * COUT; idx += 256) {
            int cr = idx >> 7, o = idx & 127;
            Ws[cr][o] = wtm[(size_t)(cc + cr) * COUT + o];
        }
        __syncthreads();
#pragma unroll
        for (int c = 0; c < 32; c++) {
            float xv[4];
#pragma unroll
            for (int i = 0; i < 4; i++) xv[i] = xsT[cc + c][b0 + i];
            float4 wv = *(const float4*)&Ws[c][o4];
            float wj[4] = { wv.x, wv.y, wv.z, wv.w };
#pragma unroll
            for (int i = 0; i < 4; i++)
#pragma unroll
                for (int j = 0; j < 4; j++) acc[i][j] += xv[i] * wj[j];
        }
    }
#pragma unroll
    for (int i = 0; i < 4; i++)
#pragma unroll
        for (int j = 0; j < 4; j++)
            g_ospec[((size_t)(b0 + i) * MM + m) * COUT + o4 + j] = tf32r(acc[i][j]);
}

// ===========================================================================
// Launch
// ===========================================================================
static constexpr int SMEM_GA = 2 * (32 * 136 + 32 * 68) * 4;   // 52224 B
static constexpr int SMEM_GC = 2 * (128 * 36 + 32 * 68) * 4;   // 54272 B

extern "C" void kernel_launch(void* const* d_in, const int* in_sizes, int n_in,
                              void* d_out, int out_size) {
    const float* x = (const float*)d_in[0];   // [32,4096,128]
    const float* U = (const float*)d_in[1];   // [4096,256]
    const float* W = (const float*)d_in[2];   // [128,128,256] (W_imag d_in[3] is dead)
    float* out = (float*)d_out;               // [32,4096,128]

    float* dUr; cudaGetSymbolAddress((void**)&dUr, g_Ur);       // host-side, capture-safe
    float* dxr; cudaGetSymbolAddress((void**)&dxr, g_xr);
    float* dxs; cudaGetSymbolAddress((void**)&dxs, g_xspec);
    float* dos; cudaGetSymbolAddress((void**)&dos, g_ospec);

    cudaFuncSetAttribute((const void*)kGemm<true, NN>,
                         cudaFuncAttributeMaxDynamicSharedMemorySize, SMEM_GA);
    cudaFuncSetAttribute((const void*)kGemm<false, MM>,
                         cudaFuncAttributeMaxDynamicSharedMemorySize, SMEM_GC);

    // tf32 pre-rounding (round-to-nearest; avoids biased in-loop truncation)
    kRound<<<512, 256>>>(U, dUr, NN * MM / 4);
    kRound<<<2048, 256>>>(x, dxr, (int)((size_t)BB * NN * CIN / 4));
    kT<<<dim3(CIN, COUT / 32, MM / 32), dim3(32, 8)>>>(W);

    // Stage A: xspec[b][m][c] = sum_n U[n][m] * x[b][n][c]   (A from [k][m] layout)
    kGemm<true, NN><<<dim3(MM / 128, CIN / 64, BB), 256, SMEM_GA>>>(
        dUr, dxr, dxs, MM, CIN, CIN, (size_t)NN * CIN, (size_t)MM * CIN);

    // Stage B (fp32) + tf32-rounded store
    kB<<<MM, 256>>>();

    // Stage C: out[b][n][o] = sum_m U[n][m] * ospec[b][m][o]  (A row-major)
    kGemm<false, MM><<<dim3(NN / 128, COUT / 64, BB), 256, SMEM_GC>>>(
        dUr, dos, out, MM, COUT, COUT, (size_t)MM * COUT, (size_t)NN * COUT);
}

// round 8
// speedup vs baseline: 4.0572x; 2.1759x over previous
#include <cuda_runtime.h>
#include <cstdint>

#define BB   32
#define NN   4096
#define CIN  128
#define COUT 128
#define MM   256
#define SPLITK_A 4

__device__ __forceinline__ float tf32r(float f) {
    uint32_t u;
    asm("cvt.rna.tf32.f32 %0, %1;" : "=r"(u) : "f"(f));
    return __uint_as_float(u);
}
__device__ __forceinline__ uint32_t tf32r_u(uint32_t v) {
    uint32_t r;
    asm("cvt.rna.tf32.f32 %0, %1;" : "=r"(r) : "f"(__uint_as_float(v)));
    return r;
}
__device__ __forceinline__ uint32_t smem_to_u32(const void* p) {
    uint32_t a;
    asm("{ .reg .u64 t; cvta.to.shared.u64 t, %1; cvt.u32.u64 %0, t; }" : "=r"(a) : "l"(p));
    return a;
}

// ===========================================================================
// Scratch (device globals — allocation-guard safe)
// ===========================================================================
__device__ __align__(16) float g_Ur[NN * MM];                          // tf32-rounded U [n][m]
__device__ __align__(16) float g_xsp[BB * SPLITK_A * MM * CIN];        // stage-A split-K partials
__device__ __align__(16) float g_wt[MM * CIN * COUT];                  // [m][c][o]
__device__ __align__(16) float g_ospec[BB * MM * COUT];                // [b][m][o] tf32-rounded

// ===========================================================================
// kRound: U -> tf32(RN)
// ===========================================================================
__global__ __launch_bounds__(256) void kRound(const float* __restrict__ src,
                                              float* __restrict__ dst, int n4) {
    for (int i = blockIdx.x * blockDim.x + threadIdx.x; i < n4; i += gridDim.x * blockDim.x) {
        float4 v = ((const float4*)src)[i];
        v.x = tf32r(v.x); v.y = tf32r(v.y); v.z = tf32r(v.z); v.w = tf32r(v.w);
        ((float4*)dst)[i] = v;
    }
}

// ===========================================================================
// kT: W_real[c][o][m] -> g_wt[m][c][o]
// ===========================================================================
__global__ __launch_bounds__(256) void kT(const float* __restrict__ W) {
    __shared__ float tile[32][33];
    const int c = blockIdx.x, o0 = blockIdx.y * 32, m0 = blockIdx.z * 32;
    const int tx = threadIdx.x, ty = threadIdx.y;
#pragma unroll
    for (int j = 0; j < 32; j += 8)
        tile[ty + j][tx] = W[((size_t)c * COUT + (o0 + ty + j)) * MM + m0 + tx];
    __syncthreads();
#pragma unroll
    for (int j = 0; j < 32; j += 8)
        g_wt[((size_t)(m0 + ty + j) * CIN + c) * COUT + o0 + tx] = tile[tx][ty + j];
}

// ===========================================================================
// tf32 GEMM: CTA 128(i) x 128(j), 4 warps of 64x64, BK=32, double-buffered.
//   C[z][i][j] = sum_{k in slice} A(i,k) * B[b][k][j],  b = z / SPLITK,
//   slice s = z % SPLITK covers k in [s*KCTA, (s+1)*KCTA).
//   ATRANS=true : gA [K][lda] (A(i,k)=gA[k*lda+i]);  false: gA [I][lda].
//   CVTB : round B fragments to tf32 in-register (B source is raw fp32).
// ===========================================================================
template <bool ATRANS, bool CVTB, int KCTA, int SPLITK>
__global__ __launch_bounds__(128, 2) void kGemm(
    const float* __restrict__ gA, const float* __restrict__ gB, float* __restrict__ gC,
    int lda, int ldb, int ldc, size_t strideB, size_t strideC)
{
    constexpr int ASZ = ATRANS ? 32 * 136 : 128 * 36;
    constexpr int BSZ = 32 * 136;
    constexpr int BUFST = ASZ + BSZ;
    extern __shared__ float sm[];
    const uint32_t smU = smem_to_u32(sm);

    const int tid = threadIdx.x;
    const int w = tid >> 5, lane = tid & 31;
    const int m_w = (w & 1) * 64, j_w = (w >> 1) * 64;
    const int r4 = lane >> 2, c4 = lane & 3;

    const int i0 = blockIdx.x * 128;
    const int z  = blockIdx.z;
    const int b  = z / SPLITK;
    const int kbase = (z - b * SPLITK) * KCTA;
    const float* gBb = gB + (size_t)b * strideB;

    float acc[4][8][4];
#pragma unroll
    for (int mt = 0; mt < 4; mt++)
#pragma unroll
        for (int nt = 0; nt < 8; nt++)
#pragma unroll
            for (int q = 0; q < 4; q++) acc[mt][nt][q] = 0.f;

    auto load = [&](int k0, int buf) {
        uint32_t aU = smU + (uint32_t)(buf * BUFST) * 4u;
        uint32_t bU = aU + (uint32_t)ASZ * 4u;
#pragma unroll
        for (int it = 0; it < 8; it++) {     // A: 1024 x 16B
            int t4 = tid + it * 128;
            const float* src; uint32_t so;
            if (ATRANS) {
                int kr = t4 >> 5, cc = (t4 & 31) * 4;
                src = gA + (size_t)(k0 + kr) * lda + i0 + cc;
                so = (uint32_t)(kr * 136 + cc);
            } else {
                int rr = t4 >> 3, cc = (t4 & 7) * 4;
                src = gA + (size_t)(i0 + rr) * lda + k0 + cc;
                so = (uint32_t)(rr * 36 + cc);
            }
            asm volatile("cp.async.cg.shared.global [%0], [%1], 16;" :: "r"(aU + so * 4u), "l"(src));
        }
#pragma unroll
        for (int it = 0; it < 8; it++) {     // B: 1024 x 16B
            int t4 = tid + it * 128;
            int kr = t4 >> 5, cc = (t4 & 31) * 4;
            const float* src = gBb + (size_t)(k0 + kr) * ldb + cc;
            asm volatile("cp.async.cg.shared.global [%0], [%1], 16;"
                         :: "r"(bU + (uint32_t)(kr * 136 + cc) * 4u), "l"(src));
        }
        asm volatile("cp.async.commit_group;");
    };

    load(kbase, 0);
    constexpr int NCH = KCTA / 32;
    for (int ch = 0; ch < NCH; ch++) {
        const int buf = ch & 1;
        if (ch + 1 < NCH) {
            load(kbase + (ch + 1) * 32, buf ^ 1);
            asm volatile("cp.async.wait_group 1;");
        } else {
            asm volatile("cp.async.wait_group 0;");
        }
        __syncthreads();

        const float* as = sm + buf * BUFST;
        const float* bs = as + ASZ;
#pragma unroll
        for (int kk = 0; kk < 32; kk += 8) {
            uint32_t a[4][4], bf[8][2];
#pragma unroll
            for (int mt = 0; mt < 4; mt++) {
                const int ib = m_w + mt * 16 + r4;
                if (ATRANS) {
                    const float* p0 = as + (kk + c4) * 136 + ib;
                    a[mt][0] = __float_as_uint(p0[0]);
                    a[mt][1] = __float_as_uint(p0[8]);
                    a[mt][2] = __float_as_uint(p0[4 * 136]);
                    a[mt][3] = __float_as_uint(p0[4 * 136 + 8]);
                } else {
                    const float* p0 = as + ib * 36 + kk + c4;
                    a[mt][0] = __float_as_uint(p0[0]);
                    a[mt][1] = __float_as_uint(p0[8 * 36]);
                    a[mt][2] = __float_as_uint(p0[4]);
                    a[mt][3] = __float_as_uint(p0[8 * 36 + 4]);
                }
            }
#pragma unroll
            for (int nt = 0; nt < 8; nt++) {
                const float* pb = bs + (kk + c4) * 136 + j_w + nt * 8 + r4;
                uint32_t b0 = __float_as_uint(pb[0]);
                uint32_t b1 = __float_as_uint(pb[4 * 136]);
                if (CVTB) { b0 = tf32r_u(b0); b1 = tf32r_u(b1); }
                bf[nt][0] = b0; bf[nt][1] = b1;
            }
#pragma unroll
            for (int mt = 0; mt < 4; mt++)
#pragma unroll
                for (int nt = 0; nt < 8; nt++)
                    asm volatile(
                        "mma.sync.aligned.m16n8k8.row.col.f32.tf32.tf32.f32 "
                        "{%0,%1,%2,%3}, {%4,%5,%6,%7}, {%8,%9}, {%0,%1,%2,%3};"
                        : "+f"(acc[mt][nt][0]), "+f"(acc[mt][nt][1]),
                          "+f"(acc[mt][nt][2]), "+f"(acc[mt][nt][3])
                        : "r"(a[mt][0]), "r"(a[mt][1]), "r"(a[mt][2]), "r"(a[mt][3]),
                          "r"(bf[nt][0]), "r"(bf[nt][1]));
        }
        __syncthreads();
    }

    float* cb = gC + (size_t)z * strideC;
#pragma unroll
    for (int mt = 0; mt < 4; mt++)
#pragma unroll
        for (int nt = 0; nt < 8; nt++) {
            const int r = i0 + m_w + mt * 16 + r4;
            const int c = j_w + nt * 8 + c4 * 2;
            float2 v0 = { acc[mt][nt][0], acc[mt][nt][1] };
            float2 v1 = { acc[mt][nt][2], acc[mt][nt][3] };
            *(float2*)&cb[(size_t)r * ldc + c] = v0;
            *(float2*)&cb[(size_t)(r + 8) * ldc + c] = v1;
        }
}

// ===========================================================================
// Stage B (fp32): ospec[b][m][o] = sum_c (sum_s xsp[b][s][m][c]) * wt[m][c][o]
// Output stored tf32-rounded for stage C.
// ===========================================================================
__global__ __launch_bounds__(256) void kB() {
    __shared__ float xsT[CIN][33];
    __shared__ float Ws[32][COUT];

    const int m = blockIdx.x;
    const int t = threadIdx.x;
    const int o4 = (t & 31) * 4;
    const int b0 = (t >> 5) * 4;

    for (int idx = t; idx < BB * CIN; idx += 256) {
        int b = idx / CIN, c = idx % CIN;
        float v = 0.f;
#pragma unroll
        for (int s = 0; s < SPLITK_A; s++)
            v += g_xsp[(((size_t)b * SPLITK_A + s) * MM + m) * CIN + c];
        xsT[c][b] = v;
    }

    float acc[4][4];
#pragma unroll
    for (int i = 0; i < 4; i++)
#pragma unroll
        for (int j = 0; j < 4; j++) acc[i][j] = 0.f;

    const float* wtm = g_wt + (size_t)m * CIN * COUT;
    for (int cc = 0; cc < CIN; cc += 32) {
        __syncthreads();
        for (int idx = t; idx < 32 * COUT; idx += 256) {
            int cr = idx >> 7, o = idx & 127;
            Ws[cr][o] = wtm[(size_t)(cc + cr) * COUT + o];
        }
        __syncthreads();
#pragma unroll
        for (int c = 0; c < 32; c++) {
            float xv[4];
#pragma unroll
            for (int i = 0; i < 4; i++) xv[i] = xsT[cc + c][b0 + i];
            float4 wv = *(const float4*)&Ws[c][o4];
            float wj[4] = { wv.x, wv.y, wv.z, wv.w };
#pragma unroll
            for (int i = 0; i < 4; i++)
#pragma unroll
                for (int j = 0; j < 4; j++) acc[i][j] += xv[i] * wj[j];
        }
    }
#pragma unroll
    for (int i = 0; i < 4; i++)
#pragma unroll
        for (int j = 0; j < 4; j++)
            g_ospec[((size_t)(b0 + i) * MM + m) * COUT + o4 + j] = tf32r(acc[i][j]);
}

// ===========================================================================
// Launch
// ===========================================================================
static constexpr int SMEM_GA = 2 * (32 * 136 + 32 * 136) * 4;    // 69632 B
static constexpr int SMEM_GC = 2 * (128 * 36 + 32 * 136) * 4;    // 71680 B

extern "C" void kernel_launch(void* const* d_in, const int* in_sizes, int n_in,
                              void* d_out, int out_size) {
    const float* x = (const float*)d_in[0];   // [32,4096,128]
    const float* U = (const float*)d_in[1];   // [4096,256]
    const float* W = (const float*)d_in[2];   // [128,128,256] (W_imag d_in[3] is dead)
    float* out = (float*)d_out;               // [32,4096,128]

    float* dUr;  cudaGetSymbolAddress((void**)&dUr,  g_Ur);
    float* dxsp; cudaGetSymbolAddress((void**)&dxsp, g_xsp);
    float* dos;  cudaGetSymbolAddress((void**)&dos,  g_ospec);

    cudaFuncSetAttribute((const void*)kGemm<true,  true,  NN / SPLITK_A, SPLITK_A>,
                         cudaFuncAttributeMaxDynamicSharedMemorySize, SMEM_GA);
    cudaFuncSetAttribute((const void*)kGemm<false, false, MM, 1>,
                         cudaFuncAttributeMaxDynamicSharedMemorySize, SMEM_GC);

    // Prep: round U once (x is rounded in-register inside stage A)
    kRound<<<256, 256>>>(U, dUr, NN * MM / 4);
    kT<<<dim3(CIN, COUT / 32, MM / 32), dim3(32, 8)>>>(W);

    // Stage A: xsp[b][s][m][c] partials = sum_{n slice} U[n][m] * x[b][n][c]
    //   A = Ur [k=n][m] (ATRANS), B = raw x (CVTB). Grid 2 x 1 x 128 = 256 CTAs.
    kGemm<true, true, NN / SPLITK_A, SPLITK_A>
        <<<dim3(MM / 128, 1, BB * SPLITK_A), 128, SMEM_GA>>>(
            dUr, x, dxsp, MM, CIN, CIN, (size_t)NN * CIN, (size_t)MM * CIN);

    // Stage B: fold split-K partials, per-mode channel mix, tf32-rounded store
    kB<<<MM, 256>>>();

    // Stage C: out[b][n][o] = sum_m U[n][m] * ospec[b][m][o]. Grid 32 x 1 x 32.
    kGemm<false, false, MM, 1>
        <<<dim3(NN / 128, 1, BB), 128, SMEM_GC>>>(
            dUr, dos, out, MM, COUT, COUT, (size_t)MM * COUT, (size_t)NN * COUT);
}

// round 9
// speedup vs baseline: 4.2862x; 1.0564x over previous
#include <cuda_runtime.h>
#include <cstdint>

#define BB   32
#define NN   4096
#define CIN  128
#define COUT 128
#define MM   256
#define SPLITK_A 4

__device__ __forceinline__ float tf32r(float f) {
    uint32_t u;
    asm("cvt.rna.tf32.f32 %0, %1;" : "=r"(u) : "f"(f));
    return __uint_as_float(u);
}
__device__ __forceinline__ uint32_t tf32r_u(uint32_t v) {
    uint32_t r;
    asm("cvt.rna.tf32.f32 %0, %1;" : "=r"(r) : "f"(__uint_as_float(v)));
    return r;
}
__device__ __forceinline__ uint32_t smem_to_u32(const void* p) {
    uint32_t a;
    asm("{ .reg .u64 t; cvta.to.shared.u64 t, %1; cvt.u32.u64 %0, t; }" : "=r"(a) : "l"(p));
    return a;
}

// ===========================================================================
// Scratch (device globals — allocation-guard safe)
// ===========================================================================
__device__ __align__(16) float g_Ur[NN * MM];                          // tf32-rounded U [n][m]
__device__ __align__(16) float g_xsp[BB * SPLITK_A * MM * CIN];        // stage-A split-K partials
__device__ __align__(16) float g_wt[MM * CIN * COUT];                  // [m][c][o]
__device__ __align__(16) float g_ospec[BB * MM * COUT];                // [b][m][o] tf32-rounded

// ===========================================================================
// kRound: U -> tf32(RN)
// ===========================================================================
__global__ __launch_bounds__(256) void kRound(const float* __restrict__ src,
                                              float* __restrict__ dst, int n4) {
    for (int i = blockIdx.x * blockDim.x + threadIdx.x; i < n4; i += gridDim.x * blockDim.x) {
        float4 v = ((const float4*)src)[i];
        v.x = tf32r(v.x); v.y = tf32r(v.y); v.z = tf32r(v.z); v.w = tf32r(v.w);
        ((float4*)dst)[i] = v;
    }
}

// ===========================================================================
// kT: W_real[c][o][m] -> g_wt[m][c][o]
// ===========================================================================
__global__ __launch_bounds__(256) void kT(const float* __restrict__ W) {
    __shared__ float tile[32][33];
    const int c = blockIdx.x, o0 = blockIdx.y * 32, m0 = blockIdx.z * 32;
    const int tx = threadIdx.x, ty = threadIdx.y;
#pragma unroll
    for (int j = 0; j < 32; j += 8)
        tile[ty + j][tx] = W[((size_t)c * COUT + (o0 + ty + j)) * MM + m0 + tx];
    __syncthreads();
#pragma unroll
    for (int j = 0; j < 32; j += 8)
        g_wt[((size_t)(m0 + ty + j) * CIN + c) * COUT + o0 + tx] = tile[tx][ty + j];
}

// ===========================================================================
// tf32 GEMM (unchanged from R8): CTA 128x128, 4 warps of 64x64, BK=32.
// ===========================================================================
template <bool ATRANS, bool CVTB, int KCTA, int SPLITK>
__global__ __launch_bounds__(128, 2) void kGemm(
    const float* __restrict__ gA, const float* __restrict__ gB, float* __restrict__ gC,
    int lda, int ldb, int ldc, size_t strideB, size_t strideC)
{
    constexpr int ASZ = ATRANS ? 32 * 136 : 128 * 36;
    constexpr int BSZ = 32 * 136;
    constexpr int BUFST = ASZ + BSZ;
    extern __shared__ float sm[];
    const uint32_t smU = smem_to_u32(sm);

    const int tid = threadIdx.x;
    const int w = tid >> 5, lane = tid & 31;
    const int m_w = (w & 1) * 64, j_w = (w >> 1) * 64;
    const int r4 = lane >> 2, c4 = lane & 3;

    const int i0 = blockIdx.x * 128;
    const int z  = blockIdx.z;
    const int b  = z / SPLITK;
    const int kbase = (z - b * SPLITK) * KCTA;
    const float* gBb = gB + (size_t)b * strideB;

    float acc[4][8][4];
#pragma unroll
    for (int mt = 0; mt < 4; mt++)
#pragma unroll
        for (int nt = 0; nt < 8; nt++)
#pragma unroll
            for (int q = 0; q < 4; q++) acc[mt][nt][q] = 0.f;

    auto load = [&](int k0, int buf) {
        uint32_t aU = smU + (uint32_t)(buf * BUFST) * 4u;
        uint32_t bU = aU + (uint32_t)ASZ * 4u;
#pragma unroll
        for (int it = 0; it < 8; it++) {
            int t4 = tid + it * 128;
            const float* src; uint32_t so;
            if (ATRANS) {
                int kr = t4 >> 5, cc = (t4 & 31) * 4;
                src = gA + (size_t)(k0 + kr) * lda + i0 + cc;
                so = (uint32_t)(kr * 136 + cc);
            } else {
                int rr = t4 >> 3, cc = (t4 & 7) * 4;
                src = gA + (size_t)(i0 + rr) * lda + k0 + cc;
                so = (uint32_t)(rr * 36 + cc);
            }
            asm volatile("cp.async.cg.shared.global [%0], [%1], 16;" :: "r"(aU + so * 4u), "l"(src));
        }
#pragma unroll
        for (int it = 0; it < 8; it++) {
            int t4 = tid + it * 128;
            int kr = t4 >> 5, cc = (t4 & 31) * 4;
            const float* src = gBb + (size_t)(k0 + kr) * ldb + cc;
            asm volatile("cp.async.cg.shared.global [%0], [%1], 16;"
                         :: "r"(bU + (uint32_t)(kr * 136 + cc) * 4u), "l"(src));
        }
        asm volatile("cp.async.commit_group;");
    };

    load(kbase, 0);
    constexpr int NCH = KCTA / 32;
    for (int ch = 0; ch < NCH; ch++) {
        const int buf = ch & 1;
        if (ch + 1 < NCH) {
            load(kbase + (ch + 1) * 32, buf ^ 1);
            asm volatile("cp.async.wait_group 1;");
        } else {
            asm volatile("cp.async.wait_group 0;");
        }
        __syncthreads();

        const float* as = sm + buf * BUFST;
        const float* bs = as + ASZ;
#pragma unroll
        for (int kk = 0; kk < 32; kk += 8) {
            uint32_t a[4][4], bf[8][2];
#pragma unroll
            for (int mt = 0; mt < 4; mt++) {
                const int ib = m_w + mt * 16 + r4;
                if (ATRANS) {
                    const float* p0 = as + (kk + c4) * 136 + ib;
                    a[mt][0] = __float_as_uint(p0[0]);
                    a[mt][1] = __float_as_uint(p0[8]);
                    a[mt][2] = __float_as_uint(p0[4 * 136]);
                    a[mt][3] = __float_as_uint(p0[4 * 136 + 8]);
                } else {
                    const float* p0 = as + ib * 36 + kk + c4;
                    a[mt][0] = __float_as_uint(p0[0]);
                    a[mt][1] = __float_as_uint(p0[8 * 36]);
                    a[mt][2] = __float_as_uint(p0[4]);
                    a[mt][3] = __float_as_uint(p0[8 * 36 + 4]);
                }
            }
#pragma unroll
            for (int nt = 0; nt < 8; nt++) {
                const float* pb = bs + (kk + c4) * 136 + j_w + nt * 8 + r4;
                uint32_t b0 = __float_as_uint(pb[0]);
                uint32_t b1 = __float_as_uint(pb[4 * 136]);
                if (CVTB) { b0 = tf32r_u(b0); b1 = tf32r_u(b1); }
                bf[nt][0] = b0; bf[nt][1] = b1;
            }
#pragma unroll
            for (int mt = 0; mt < 4; mt++)
#pragma unroll
                for (int nt = 0; nt < 8; nt++)
                    asm volatile(
                        "mma.sync.aligned.m16n8k8.row.col.f32.tf32.tf32.f32 "
                        "{%0,%1,%2,%3}, {%4,%5,%6,%7}, {%8,%9}, {%0,%1,%2,%3};"
                        : "+f"(acc[mt][nt][0]), "+f"(acc[mt][nt][1]),
                          "+f"(acc[mt][nt][2]), "+f"(acc[mt][nt][3])
                        : "r"(a[mt][0]), "r"(a[mt][1]), "r"(a[mt][2]), "r"(a[mt][3]),
                          "r"(bf[nt][0]), "r"(bf[nt][1]));
        }
        __syncthreads();
    }

    float* cb = gC + (size_t)z * strideC;
#pragma unroll
    for (int mt = 0; mt < 4; mt++)
#pragma unroll
        for (int nt = 0; nt < 8; nt++) {
            const int r = i0 + m_w + mt * 16 + r4;
            const int c = j_w + nt * 8 + c4 * 2;
            float2 v0 = { acc[mt][nt][0], acc[mt][nt][1] };
            float2 v1 = { acc[mt][nt][2], acc[mt][nt][3] };
            *(float2*)&cb[(size_t)r * ldc + c] = v0;
            *(float2*)&cb[(size_t)(r + 8) * ldc + c] = v1;
        }
}

// ===========================================================================
// Stage B v2: ospec[b][m][o] = sum_c (sum_s xsp[b][s][m][c]) * wt[m][c][o]
// Grid (m, o-half) = 512 blocks. cp.async double-buffered W chunks (8 KB).
// Thread micro-tile: 4 b x 2 o.
// ===========================================================================
__global__ __launch_bounds__(256) void kB2() {
    __shared__ float xsT[CIN][33];        // [c][b]
    __shared__ __align__(16) float Ws[2][32][64];

    const int m = blockIdx.x;
    const int h = blockIdx.y;             // o-half: [h*64, h*64+64)
    const int t = threadIdx.x;
    const uint32_t wsU = smem_to_u32(Ws);

    const float* wtm = g_wt + (size_t)m * CIN * COUT + h * 64;

    // W chunk loader: rows cc..cc+31, 64 floats each (coalesced 256B rows)
    auto loadW = [&](int cc, int buf) {
#pragma unroll
        for (int it = 0; it < 2; it++) {
            int t4 = t + it * 256;              // 0..511
            int cr = t4 >> 4;                   // 0..31
            int oc = (t4 & 15) * 4;             // 0..60
            const float* src = wtm + (size_t)(cc + cr) * COUT + oc;
            asm volatile("cp.async.cg.shared.global [%0], [%1], 16;"
                         :: "r"(wsU + (uint32_t)(((buf * 32 + cr) * 64 + oc) * 4)), "l"(src));
        }
        asm volatile("cp.async.commit_group;");
    };

    loadW(0, 0);

    // Fold split-K partials into xsT[c][b] (overlaps with W chunk 0 in flight)
    for (int idx = t; idx < BB * CIN; idx += 256) {
        int b = idx >> 7, c = idx & 127;
        float v = 0.f;
#pragma unroll
        for (int s = 0; s < SPLITK_A; s++)
            v += g_xsp[(((size_t)b * SPLITK_A + s) * MM + m) * CIN + c];
        xsT[c][b] = v;
    }

    const int o2 = (t & 31) * 2;          // 0..62 within the half
    const int b0 = (t >> 5) * 4;          // 0..28

    float acc[4][2];
#pragma unroll
    for (int i = 0; i < 4; i++) { acc[i][0] = 0.f; acc[i][1] = 0.f; }

    for (int cc = 0; cc < CIN; cc += 32) {
        const int buf = (cc >> 5) & 1;
        if (cc + 32 < CIN) {
            loadW(cc + 32, buf ^ 1);
            asm volatile("cp.async.wait_group 1;");
        } else {
            asm volatile("cp.async.wait_group 0;");
        }
        __syncthreads();   // W chunk ready; also guards xsT fold on first iter

#pragma unroll
        for (int c = 0; c < 32; c++) {
            float2 wv = *(const float2*)&Ws[buf][c][o2];
            float xv[4];
#pragma unroll
            for (int i = 0; i < 4; i++) xv[i] = xsT[cc + c][b0 + i];  // broadcast
#pragma unroll
            for (int i = 0; i < 4; i++) {
                acc[i][0] += xv[i] * wv.x;
                acc[i][1] += xv[i] * wv.y;
            }
        }
        __syncthreads();
    }

#pragma unroll
    for (int i = 0; i < 4; i++) {
        float2 v = { tf32r(acc[i][0]), tf32r(acc[i][1]) };
        *(float2*)&g_ospec[((size_t)(b0 + i) * MM + m) * COUT + h * 64 + o2] = v;
    }
}

// ===========================================================================
// Launch
// ===========================================================================
static constexpr int SMEM_GA = 2 * (32 * 136 + 32 * 136) * 4;    // 69632 B
static constexpr int SMEM_GC = 2 * (128 * 36 + 32 * 136) * 4;    // 71680 B

extern "C" void kernel_launch(void* const* d_in, const int* in_sizes, int n_in,
                              void* d_out, int out_size) {
    const float* x = (const float*)d_in[0];   // [32,4096,128]
    const float* U = (const float*)d_in[1];   // [4096,256]
    const float* W = (const float*)d_in[2];   // [128,128,256] (W_imag d_in[3] is dead)
    float* out = (float*)d_out;               // [32,4096,128]

    float* dUr;  cudaGetSymbolAddress((void**)&dUr,  g_Ur);
    float* dxsp; cudaGetSymbolAddress((void**)&dxsp, g_xsp);
    float* dos;  cudaGetSymbolAddress((void**)&dos,  g_ospec);

    cudaFuncSetAttribute((const void*)kGemm<true,  true,  NN / SPLITK_A, SPLITK_A>,
                         cudaFuncAttributeMaxDynamicSharedMemorySize, SMEM_GA);
    cudaFuncSetAttribute((const void*)kGemm<false, false, MM, 1>,
                         cudaFuncAttributeMaxDynamicSharedMemorySize, SMEM_GC);

    // Prep: round U once (x is rounded in-register inside stage A)
    kRound<<<256, 256>>>(U, dUr, NN * MM / 4);
    kT<<<dim3(CIN, COUT / 32, MM / 32), dim3(32, 8)>>>(W);

    // Stage A: xsp[b][s][m][c] partials = sum_{n slice} U[n][m] * x[b][n][c]
    kGemm<true, true, NN / SPLITK_A, SPLITK_A>
        <<<dim3(MM / 128, 1, BB * SPLITK_A), 128, SMEM_GA>>>(
            dUr, x, dxsp, MM, CIN, CIN, (size_t)NN * CIN, (size_t)MM * CIN);

    // Stage B: fold partials + per-mode channel mix (512 CTAs, cp.async)
    kB2<<<dim3(MM, 2), 256>>>();

    // Stage C: out[b][n][o] = sum_m U[n][m] * ospec[b][m][o]
    kGemm<false, false, MM, 1>
        <<<dim3(NN / 128, 1, BB), 128, SMEM_GC>>>(
            dUr, dos, out, MM, COUT, COUT, (size_t)MM * COUT, (size_t)NN * COUT);
}